// round 1
// baseline (speedup 1.0000x reference)
#include <cuda_runtime.h>
#include <cuda_bf16.h>
#include <math.h>

// Shapes
#define Bsz   32
#define Ndim  64
#define Mdim  64
#define Cdim  64
#define C1dim 16
#define Hdim  256
#define INTER 912      // 2H + 6C + C1
#define NSEQ  4096     // 2 * B * N sequences through the shared 2D GRU
#define TSTEP 64

// ---------------- scratch (device globals; no cudaMalloc allowed) ----------------
__device__ float d_f[Bsz * Ndim * INTER];        // fused feature tensor [B,N,912]
__device__ float d_xW1[Bsz * Ndim * 768];        // precomputed x @ Wih1^T + bih1
__device__ float d_WhT2[256 * 768];              // gru2d Whh transposed [k][o]
__device__ float d_WiT2[64 * 768];               // gru2d Wih transposed
__device__ float d_WhT1[256 * 768];              // gru1d Whh transposed
__device__ float d_WiT1[912 * 768];              // gru1d Wih transposed
__device__ float d_fc1WT[2992 * 256];            // fc1 W transposed [j][o]
__device__ float d_hlast[Bsz * Hdim];
__device__ int   d_perm_is32;

__device__ __forceinline__ float sigm(float x) { return 1.f / (1.f + __expf(-x)); }

// ---------------- perm dtype probe (int64 vs int32) ----------------
__global__ void detect_kernel(const long long* __restrict__ p) {
    if (threadIdx.x == 0 && blockIdx.x == 0) {
        int is32 = 0;
        for (int i = 0; i < 32; ++i) {
            long long v = p[i];
            if (v < 0 || v >= 64) is32 = 1;   // int32 data read as int64 overflows range
        }
        d_perm_is32 = is32;
    }
}

// ---------------- weight transposes ----------------
// segments: WhT2(196608) WiT2(49152) WhT1(196608) WiT1(700416) fc1WT(765952)
__global__ void prep_kernel(const float* __restrict__ Whh2, const float* __restrict__ Wih2,
                            const float* __restrict__ Whh1, const float* __restrict__ Wih1,
                            const float* __restrict__ fc1W) {
    int i = blockIdx.x * blockDim.x + threadIdx.x;
    if (i < 196608) {
        int k = i / 768, o = i % 768;
        d_WhT2[i] = Whh2[o * 256 + k];
    } else if (i < 245760) {
        int j = i - 196608; int k = j / 768, o = j % 768;
        d_WiT2[j] = Wih2[o * 64 + k];
    } else if (i < 442368) {
        int j = i - 245760; int k = j / 768, o = j % 768;
        d_WhT1[j] = Whh1[o * 256 + k];
    } else if (i < 1142784) {
        int j = i - 442368; int k = j / 768, o = j % 768;
        d_WiT1[j] = Wih1[o * 912 + k];
    } else if (i < 1908736) {
        int j = i - 1142784; int o = j % 256, j2 = j / 256;
        d_fc1WT[j] = fc1W[o * 2992 + j2];
    }
}

// ---------------- pools over states + x1 copy into f ----------------
// ranges: [0,131072) axis-1 pools, [131072,262144) axis-2 pools, [262144,294912) x1 copy
__global__ void pool_kernel(const float* __restrict__ states, const float* __restrict__ x1) {
    int i = blockIdx.x * blockDim.x + threadIdx.x;
    if (i < 131072) {
        int c = i & 63, j = (i >> 6) & 63, b = i >> 12;
        float mx = -1e30f, mn = 1e30f, sm = 0.f;
        for (int n = 0; n < 64; ++n) {
            float v = states[(((b * 64 + n) * 64 + j) << 6) + c];
            mx = fmaxf(mx, v); mn = fminf(mn, v); sm += v;
        }
        float* fp = d_f + (size_t)(b * 64 + j) * INTER;
        fp[16 + c] = mx; fp[80 + c] = sm * (1.f / 64.f); fp[144 + c] = mn;
    } else if (i < 262144) {
        int i2 = i - 131072;
        int c = i2 & 63, n = (i2 >> 6) & 63, b = i2 >> 12;
        float mx = -1e30f, mn = 1e30f, sm = 0.f;
        const float* row = states + (((size_t)(b * 64 + n) * 64) << 6) + c;
        for (int m = 0; m < 64; ++m) {
            float v = row[m << 6];
            mx = fmaxf(mx, v); mn = fminf(mn, v); sm += v;
        }
        float* fp = d_f + (size_t)(b * 64 + n) * INTER;
        fp[208 + c] = mx; fp[272 + c] = sm * (1.f / 64.f); fp[336 + c] = mn;
    } else if (i < 294912) {
        int i3 = i - 262144;
        d_f[(size_t)(i3 >> 4) * INTER + (i3 & 15)] = x1[i3];
    }
}

// ---------------- fused 2D GRU: 4096 independent sequences, one launch ----------------
// 512 blocks x 256 threads; each block owns 8 sequences; h kept in SMEM for 64 steps.
__global__ void __launch_bounds__(256) gru2d_kernel(
    const float* __restrict__ states,
    const void* __restrict__ perm1v, const void* __restrict__ perm2v,
    const float* __restrict__ bih, const float* __restrict__ bhh) {
    __shared__ float hT[256][8];   // [k][seq]
    __shared__ float xT[64][8];    // [c][seq]
    const int tid = threadIdx.x;
    const int seq0 = blockIdx.x * 8;
    const int is32 = d_perm_is32;
    const long long* __restrict__ p1_64 = (const long long*)perm1v;
    const long long* __restrict__ p2_64 = (const long long*)perm2v;
    const int* __restrict__ p1_32 = (const int*)perm1v;
    const int* __restrict__ p2_32 = (const int*)perm2v;

    const float b_r  = bih[tid]       + bhh[tid];
    const float b_z  = bih[256 + tid] + bhh[256 + tid];
    const float b_in = bih[512 + tid];
    const float b_hn = bhh[512 + tid];

    for (int i = tid; i < 256 * 8; i += 256) (&hT[0][0])[i] = 0.f;

    for (int t = 0; t < TSTEP; ++t) {
        __syncthreads();
        // gather x_t for the 8 sequences (transposed into xT[c][s])
        for (int i = tid; i < 512; i += 256) {
            int si = i >> 6;
            int c  = i & 63;
            int s  = seq0 + si;
            const float* src;
            if (s < 2048) {
                int b = s >> 6, n = s & 63;
                int m = is32 ? p1_32[n * 64 + t] : (int)p1_64[n * 64 + t];
                src = states + (((size_t)((b * 64 + n) * 64 + m)) << 6);
            } else {
                int sp = s - 2048;
                int b = sp >> 6, n = sp & 63;
                int sn = is32 ? p2_32[n * 64 + t] : (int)p2_64[n * 64 + t];
                src = states + (((size_t)((b * 64 + sn) * 64 + n)) << 6);
            }
            xT[c][si] = src[c];
        }
        __syncthreads();

        float ar[8], az[8], anh[8], ani[8];
        #pragma unroll
        for (int si = 0; si < 8; ++si) { ar[si] = 0.f; az[si] = 0.f; anh[si] = 0.f; ani[si] = 0.f; }

        // recurrent part: K = 256
        #pragma unroll 4
        for (int k = 0; k < 256; ++k) {
            const float* wrow = d_WhT2 + k * 768;
            float wr = wrow[tid], wz = wrow[tid + 256], wn = wrow[tid + 512];
            float4 h0 = *reinterpret_cast<const float4*>(&hT[k][0]);
            float4 h1 = *reinterpret_cast<const float4*>(&hT[k][4]);
            float hv[8] = {h0.x, h0.y, h0.z, h0.w, h1.x, h1.y, h1.z, h1.w};
            #pragma unroll
            for (int si = 0; si < 8; ++si) {
                ar[si]  += hv[si] * wr;
                az[si]  += hv[si] * wz;
                anh[si] += hv[si] * wn;
            }
        }
        // input part: K = 64
        #pragma unroll 4
        for (int k = 0; k < 64; ++k) {
            const float* wrow = d_WiT2 + k * 768;
            float wr = wrow[tid], wz = wrow[tid + 256], wn = wrow[tid + 512];
            float4 x0 = *reinterpret_cast<const float4*>(&xT[k][0]);
            float4 x1v = *reinterpret_cast<const float4*>(&xT[k][4]);
            float xv[8] = {x0.x, x0.y, x0.z, x0.w, x1v.x, x1v.y, x1v.z, x1v.w};
            #pragma unroll
            for (int si = 0; si < 8; ++si) {
                ar[si]  += xv[si] * wr;
                az[si]  += xv[si] * wz;
                ani[si] += xv[si] * wn;
            }
        }
        __syncthreads();

        #pragma unroll
        for (int si = 0; si < 8; ++si) {
            float hold = hT[tid][si];
            float r = sigm(ar[si] + b_r);
            float z = sigm(az[si] + b_z);
            float nn = tanhf(ani[si] + b_in + r * (anh[si] + b_hn));
            float hn = (1.f - z) * nn + z * hold;
            hT[tid][si] = hn;
            if (t == TSTEP - 1) {
                int s = seq0 + si;
                int b, n, off;
                if (s < 2048) { b = s >> 6; n = s & 63; off = 400; }
                else { int sp = s - 2048; b = sp >> 6; n = sp & 63; off = 656; }
                d_f[(size_t)(b * 64 + n) * INTER + off + tid] = hn;
            }
        }
    }
}

// ---------------- xW1 = f @ Wih1^T + bih1  (M=2048, K=912, N=768) ----------------
__global__ void __launch_bounds__(256) gemm_xw1_kernel(const float* __restrict__ bih1) {
    __shared__ float As[16][64];
    __shared__ float Bs[16][64];
    const int tid = threadIdx.x;
    const int bn = blockIdx.x;     // 0..11
    const int bm = blockIdx.y;     // 0..31
    const int tx = tid & 15, ty = tid >> 4;
    float acc[4][4];
    #pragma unroll
    for (int r = 0; r < 4; ++r)
        #pragma unroll
        for (int c = 0; c < 4; ++c) acc[r][c] = 0.f;

    for (int k0 = 0; k0 < 912; k0 += 16) {
        for (int l = tid; l < 1024; l += 256) {
            int i = l >> 4, k = l & 15;
            As[k][i] = d_f[(size_t)(bm * 64 + i) * INTER + k0 + k];
        }
        for (int l = tid; l < 1024; l += 256) {
            int k = l >> 6, j = l & 63;
            Bs[k][j] = d_WiT1[(size_t)(k0 + k) * 768 + bn * 64 + j];
        }
        __syncthreads();
        #pragma unroll
        for (int k = 0; k < 16; ++k) {
            float4 a = *reinterpret_cast<const float4*>(&As[k][ty * 4]);
            float4 b = *reinterpret_cast<const float4*>(&Bs[k][tx * 4]);
            float av[4] = {a.x, a.y, a.z, a.w};
            float bv[4] = {b.x, b.y, b.z, b.w};
            #pragma unroll
            for (int r = 0; r < 4; ++r)
                #pragma unroll
                for (int c = 0; c < 4; ++c) acc[r][c] += av[r] * bv[c];
        }
        __syncthreads();
    }
    #pragma unroll
    for (int r = 0; r < 4; ++r) {
        int m = bm * 64 + ty * 4 + r;
        #pragma unroll
        for (int c = 0; c < 4; ++c) {
            int o = bn * 64 + tx * 4 + c;
            d_xW1[(size_t)m * 768 + o] = acc[r][c] + bih1[o];
        }
    }
}

// ---------------- fused 1D GRU: 32 independent batch rows, one launch ----------------
__global__ void __launch_bounds__(192) gru1d_kernel(const float* __restrict__ bhh) {
    __shared__ float h[256];
    __shared__ float gh[768];
    const int tid = threadIdx.x;
    const int b = blockIdx.x;
    const float* __restrict__ xW = d_xW1 + (size_t)b * 64 * 768;
    const int o = tid * 4;

    for (int i = tid; i < 256; i += 192) h[i] = 0.f;
    __syncthreads();

    for (int t = 0; t < TSTEP; ++t) {
        float4 acc = make_float4(bhh[o], bhh[o + 1], bhh[o + 2], bhh[o + 3]);
        #pragma unroll 4
        for (int k = 0; k < 256; ++k) {
            float hk = h[k];
            float4 w = *reinterpret_cast<const float4*>(&d_WhT1[(size_t)k * 768 + o]);
            acc.x += hk * w.x; acc.y += hk * w.y; acc.z += hk * w.z; acc.w += hk * w.w;
        }
        *reinterpret_cast<float4*>(&gh[o]) = acc;
        __syncthreads();
        const float* xwt = xW + t * 768;
        for (int j = tid; j < 256; j += 192) {
            float r = sigm(xwt[j] + gh[j]);
            float z = sigm(xwt[256 + j] + gh[256 + j]);
            float nn = tanhf(xwt[512 + j] + r * gh[512 + j]);
            h[j] = (1.f - z) * nn + z * h[j];
        }
        __syncthreads();
    }
    for (int i = tid; i < 256; i += 192) d_hlast[b * 256 + i] = h[i];
}

// ---------------- final pools over f + fc1 + fc2 ----------------
__global__ void __launch_bounds__(256) final_kernel(const float* __restrict__ fc1b,
                                                    const float* __restrict__ fc2W,
                                                    const float* __restrict__ fc2b,
                                                    float* __restrict__ out) {
    __shared__ float g[2992];
    __shared__ float hh[256];
    __shared__ float red[8];
    const int b = blockIdx.x, tid = threadIdx.x;
    const float* fb = d_f + (size_t)b * 64 * INTER;

    for (int c = tid; c < INTER; c += 256) {
        float mx = -1e30f, mn = 1e30f, sm = 0.f;
        for (int n = 0; n < 64; ++n) {
            float v = fb[n * INTER + c];
            mx = fmaxf(mx, v); mn = fminf(mn, v); sm += v;
        }
        g[c] = mx; g[912 + c] = sm * (1.f / 64.f); g[1824 + c] = mn;
    }
    g[2736 + tid] = d_hlast[b * 256 + tid];
    __syncthreads();

    float acc = fc1b[tid];
    #pragma unroll 4
    for (int j = 0; j < 2992; ++j) acc += g[j] * d_fc1WT[(size_t)j * 256 + tid];
    hh[tid] = fmaxf(acc, 0.f);
    __syncthreads();

    float v = hh[tid] * fc2W[tid];
    #pragma unroll
    for (int off = 16; off > 0; off >>= 1) v += __shfl_down_sync(0xffffffffu, v, off);
    if ((tid & 31) == 0) red[tid >> 5] = v;
    __syncthreads();
    if (tid == 0) {
        float s = 0.f;
        #pragma unroll
        for (int i = 0; i < 8; ++i) s += red[i];
        out[b] = s + fc2b[0];
    }
}

// ---------------- launch ----------------
extern "C" void kernel_launch(void* const* d_in, const int* in_sizes, int n_in,
                              void* d_out, int out_size) {
    const float* x1     = (const float*)d_in[0];
    const float* states = (const float*)d_in[1];
    const void*  perm1  = d_in[2];
    const void*  perm2  = d_in[3];
    const float* Wih2   = (const float*)d_in[4];
    const float* Whh2   = (const float*)d_in[5];
    const float* bih2   = (const float*)d_in[6];
    const float* bhh2   = (const float*)d_in[7];
    const float* Wih1   = (const float*)d_in[8];
    const float* Whh1   = (const float*)d_in[9];
    const float* bih1   = (const float*)d_in[10];
    const float* bhh1   = (const float*)d_in[11];
    const float* fc1W   = (const float*)d_in[12];
    const float* fc1b   = (const float*)d_in[13];
    const float* fc2W   = (const float*)d_in[14];
    const float* fc2b   = (const float*)d_in[15];
    float* out = (float*)d_out;

    detect_kernel<<<1, 32>>>((const long long*)perm1);
    prep_kernel<<<7456, 256>>>(Whh2, Wih2, Whh1, Wih1, fc1W);
    pool_kernel<<<1152, 256>>>(states, x1);
    gru2d_kernel<<<512, 256>>>(states, perm1, perm2, bih2, bhh2);
    gemm_xw1_kernel<<<dim3(12, 32), 256>>>(bih1);
    gru1d_kernel<<<32, 192>>>(bhh1);
    final_kernel<<<32, 256>>>(fc1b, fc2W, fc2b, out);
}

// round 2
// speedup vs baseline: 1.3782x; 1.3782x over previous
#include <cuda_runtime.h>
#include <cuda_bf16.h>
#include <math.h>

typedef unsigned long long ull;

// Shapes
#define Bsz   32
#define Ndim  64
#define Mdim  64
#define Cdim  64
#define C1dim 16
#define Hdim  256
#define INTER 912      // 2H + 6C + C1
#define NSEQ  4096     // 2 * B * N sequences through the shared 2D GRU
#define TSTEP 64

// f32x2 packed helpers (sm_100+ PTX; ptxas won't auto-fuse)
#define FFMA2(acc, a, b)   asm("fma.rn.f32x2 %0, %1, %2, %0;" : "+l"(acc) : "l"(a), "l"(b))
#define ADD2(d, a, b)      asm("add.rn.f32x2 %0, %1, %2;" : "=l"(d) : "l"(a), "l"(b))
#define PACK1(d, s)        asm("mov.b64 %0, {%1, %1};" : "=l"(d) : "f"(s))
#define PACKAB(d, lo, hi)  asm("mov.b64 %0, {%1, %2};" : "=l"(d) : "f"(lo), "f"(hi))
#define UNPACK2(lo, hi, s) asm("mov.b64 {%0, %1}, %2;" : "=f"(lo), "=f"(hi) : "l"(s))

// ---------------- scratch (device globals; no cudaMalloc allowed) ----------------
__device__ float d_f[Bsz * Ndim * INTER];        // fused feature tensor [B,N,912]
__device__ float d_xW1[Bsz * Ndim * 768];        // precomputed f @ Wih1^T + bih1
__device__ float d_WhT2[256 * 768];              // gru2d Whh transposed [k][o]
__device__ float d_WiT2[64 * 768];               // gru2d Wih transposed
__device__ float d_WhT1[256 * 768];              // gru1d Whh transposed
__device__ float d_WiT1[912 * 768];              // gru1d Wih transposed
__device__ float d_fc1WT[2992 * 256];            // fc1 W transposed [j][o]
__device__ float d_hlast[Bsz * Hdim];
__device__ int   d_perm_is32;

__device__ __forceinline__ float sigm(float x) { return 1.f / (1.f + __expf(-x)); }

// ---------------- perm dtype probe (int64 vs int32) ----------------
__global__ void detect_kernel(const long long* __restrict__ p) {
    if (threadIdx.x == 0 && blockIdx.x == 0) {
        int is32 = 0;
        for (int i = 0; i < 32; ++i) {
            long long v = p[i];
            if (v < 0 || v >= 64) is32 = 1;   // int32 data read as int64 overflows range
        }
        d_perm_is32 = is32;
    }
}

// ---------------- weight transposes ----------------
__global__ void prep_kernel(const float* __restrict__ Whh2, const float* __restrict__ Wih2,
                            const float* __restrict__ Whh1, const float* __restrict__ Wih1,
                            const float* __restrict__ fc1W) {
    int i = blockIdx.x * blockDim.x + threadIdx.x;
    if (i < 196608) {
        int k = i / 768, o = i % 768;
        d_WhT2[i] = Whh2[o * 256 + k];
    } else if (i < 245760) {
        int j = i - 196608; int k = j / 768, o = j % 768;
        d_WiT2[j] = Wih2[o * 64 + k];
    } else if (i < 442368) {
        int j = i - 245760; int k = j / 768, o = j % 768;
        d_WhT1[j] = Whh1[o * 256 + k];
    } else if (i < 1142784) {
        int j = i - 442368; int k = j / 768, o = j % 768;
        d_WiT1[j] = Wih1[o * 912 + k];
    } else if (i < 1908736) {
        int j = i - 1142784; int o = j % 256, j2 = j / 256;
        d_fc1WT[j] = fc1W[o * 2992 + j2];
    }
}

// ---------------- pools over states + x1 copy into f ----------------
__global__ void pool_kernel(const float* __restrict__ states, const float* __restrict__ x1) {
    int i = blockIdx.x * blockDim.x + threadIdx.x;
    if (i < 131072) {
        int c = i & 63, j = (i >> 6) & 63, b = i >> 12;
        float mx = -1e30f, mn = 1e30f, sm = 0.f;
        for (int n = 0; n < 64; ++n) {
            float v = states[(((b * 64 + n) * 64 + j) << 6) + c];
            mx = fmaxf(mx, v); mn = fminf(mn, v); sm += v;
        }
        float* fp = d_f + (size_t)(b * 64 + j) * INTER;
        fp[16 + c] = mx; fp[80 + c] = sm * (1.f / 64.f); fp[144 + c] = mn;
    } else if (i < 262144) {
        int i2 = i - 131072;
        int c = i2 & 63, n = (i2 >> 6) & 63, b = i2 >> 12;
        float mx = -1e30f, mn = 1e30f, sm = 0.f;
        const float* row = states + (((size_t)(b * 64 + n) * 64) << 6) + c;
        for (int m = 0; m < 64; ++m) {
            float v = row[m << 6];
            mx = fmaxf(mx, v); mn = fminf(mn, v); sm += v;
        }
        float* fp = d_f + (size_t)(b * 64 + n) * INTER;
        fp[208 + c] = mx; fp[272 + c] = sm * (1.f / 64.f); fp[336 + c] = mn;
    } else if (i < 294912) {
        int i3 = i - 262144;
        d_f[(size_t)(i3 >> 4) * INTER + (i3 & 15)] = x1[i3];
    }
}

// ---------------- fused 2D GRU: 4096 seqs, 16 per block, f32x2 math ----------------
__global__ void __launch_bounds__(256, 2) gru2d_kernel(
    const float* __restrict__ states,
    const void* __restrict__ perm1v, const void* __restrict__ perm2v,
    const float* __restrict__ bih, const float* __restrict__ bhh) {
    __shared__ float hT[256][16];   // [k][seq]
    __shared__ float xT[64][16];    // [c][seq]
    const int tid = threadIdx.x;
    const int seq0 = blockIdx.x * 16;
    const int is32 = d_perm_is32;
    const long long* __restrict__ p1_64 = (const long long*)perm1v;
    const long long* __restrict__ p2_64 = (const long long*)perm2v;
    const int* __restrict__ p1_32 = (const int*)perm1v;
    const int* __restrict__ p2_32 = (const int*)perm2v;

    const float b_r  = bih[tid]       + bhh[tid];
    const float b_z  = bih[256 + tid] + bhh[256 + tid];
    const float b_in = bih[512 + tid];
    const float b_hn = bhh[512 + tid];

    const int fbase = (seq0 < 2048) ? seq0 : (seq0 - 2048);
    const int foff  = (seq0 < 2048) ? 400  : 656;

    for (int i = tid; i < 256 * 16; i += 256) (&hT[0][0])[i] = 0.f;

    for (int t = 0; t < TSTEP; ++t) {
        __syncthreads();
        // gather x_t for the 16 sequences (transposed into xT[c][si])
        for (int i = tid; i < 1024; i += 256) {
            int si = i >> 6;
            int c  = i & 63;
            int s  = seq0 + si;
            const float* src;
            if (s < 2048) {
                int b = s >> 6, n = s & 63;
                int m = is32 ? p1_32[n * 64 + t] : (int)p1_64[n * 64 + t];
                src = states + (((size_t)((b * 64 + n) * 64 + m)) << 6);
            } else {
                int sp = s - 2048;
                int b = sp >> 6, n = sp & 63;
                int sn = is32 ? p2_32[n * 64 + t] : (int)p2_64[n * 64 + t];
                src = states + (((size_t)((b * 64 + sn) * 64 + n)) << 6);
            }
            xT[c][si] = src[c];
        }
        __syncthreads();

        ull accr[8], accz[8], accn[8], acci[8];
        #pragma unroll
        for (int p = 0; p < 8; ++p) { accr[p] = 0ull; accz[p] = 0ull; accn[p] = 0ull; acci[p] = 0ull; }

        // recurrent part: K = 256
        #pragma unroll 2
        for (int k = 0; k < 256; ++k) {
            const float* wrow = d_WhT2 + k * 768;
            ull wr, wz, wn;
            PACK1(wr, wrow[tid]);
            PACK1(wz, wrow[tid + 256]);
            PACK1(wn, wrow[tid + 512]);
            const ulonglong2* hp = (const ulonglong2*)&hT[k][0];
            ulonglong2 h0 = hp[0], h1 = hp[1], h2 = hp[2], h3 = hp[3];
            ull hv[8] = {h0.x, h0.y, h1.x, h1.y, h2.x, h2.y, h3.x, h3.y};
            #pragma unroll
            for (int p = 0; p < 8; ++p) {
                FFMA2(accr[p], hv[p], wr);
                FFMA2(accz[p], hv[p], wz);
                FFMA2(accn[p], hv[p], wn);
            }
        }
        // input part: K = 64
        #pragma unroll 2
        for (int k = 0; k < 64; ++k) {
            const float* wrow = d_WiT2 + k * 768;
            ull wr, wz, wn;
            PACK1(wr, wrow[tid]);
            PACK1(wz, wrow[tid + 256]);
            PACK1(wn, wrow[tid + 512]);
            const ulonglong2* xp = (const ulonglong2*)&xT[k][0];
            ulonglong2 x0 = xp[0], x1 = xp[1], x2 = xp[2], x3 = xp[3];
            ull xv[8] = {x0.x, x0.y, x1.x, x1.y, x2.x, x2.y, x3.x, x3.y};
            #pragma unroll
            for (int p = 0; p < 8; ++p) {
                FFMA2(accr[p], xv[p], wr);
                FFMA2(accz[p], xv[p], wz);
                FFMA2(acci[p], xv[p], wn);
            }
        }
        __syncthreads();

        // epilogue: activations + h update for 16 seqs (channel = tid)
        float hold[16];
        {
            const float4* hrow = (const float4*)&hT[tid][0];
            float4 a = hrow[0], b4 = hrow[1], c4 = hrow[2], d4 = hrow[3];
            hold[0]=a.x; hold[1]=a.y; hold[2]=a.z; hold[3]=a.w;
            hold[4]=b4.x; hold[5]=b4.y; hold[6]=b4.z; hold[7]=b4.w;
            hold[8]=c4.x; hold[9]=c4.y; hold[10]=c4.z; hold[11]=c4.w;
            hold[12]=d4.x; hold[13]=d4.y; hold[14]=d4.z; hold[15]=d4.w;
        }
        float hnew[16];
        #pragma unroll
        for (int p = 0; p < 8; ++p) {
            float ar0, ar1, az0, az1, ah0, ah1, ai0, ai1;
            UNPACK2(ar0, ar1, accr[p]);
            UNPACK2(az0, az1, accz[p]);
            UNPACK2(ah0, ah1, accn[p]);
            UNPACK2(ai0, ai1, acci[p]);
            float r0 = sigm(ar0 + b_r);
            float z0 = sigm(az0 + b_z);
            float n0 = tanhf(ai0 + b_in + r0 * (ah0 + b_hn));
            hnew[2 * p]     = (1.f - z0) * n0 + z0 * hold[2 * p];
            float r1 = sigm(ar1 + b_r);
            float z1 = sigm(az1 + b_z);
            float n1 = tanhf(ai1 + b_in + r1 * (ah1 + b_hn));
            hnew[2 * p + 1] = (1.f - z1) * n1 + z1 * hold[2 * p + 1];
        }
        {
            float4* hw = (float4*)&hT[tid][0];
            hw[0] = make_float4(hnew[0], hnew[1], hnew[2], hnew[3]);
            hw[1] = make_float4(hnew[4], hnew[5], hnew[6], hnew[7]);
            hw[2] = make_float4(hnew[8], hnew[9], hnew[10], hnew[11]);
            hw[3] = make_float4(hnew[12], hnew[13], hnew[14], hnew[15]);
        }
        if (t == TSTEP - 1) {
            #pragma unroll
            for (int si = 0; si < 16; ++si)
                d_f[(size_t)(fbase + si) * INTER + foff + tid] = hnew[si];
        }
    }
}

// ---------------- xW1 = f @ Wih1^T + bih1  (M=2048, K=912, N=768) ----------------
__global__ void __launch_bounds__(256) gemm_xw1_kernel(const float* __restrict__ bih1) {
    __shared__ float As[16][64];
    __shared__ float Bs[16][64];
    const int tid = threadIdx.x;
    const int bn = blockIdx.x;     // 0..11
    const int bm = blockIdx.y;     // 0..31
    const int tx = tid & 15, ty = tid >> 4;
    ull acc2[4][2];
    #pragma unroll
    for (int r = 0; r < 4; ++r) { acc2[r][0] = 0ull; acc2[r][1] = 0ull; }

    for (int k0 = 0; k0 < 912; k0 += 16) {
        for (int l = tid; l < 1024; l += 256) {
            int i = l >> 4, k = l & 15;
            As[k][i] = d_f[(size_t)(bm * 64 + i) * INTER + k0 + k];
        }
        for (int l = tid; l < 1024; l += 256) {
            int k = l >> 6, j = l & 63;
            Bs[k][j] = d_WiT1[(size_t)(k0 + k) * 768 + bn * 64 + j];
        }
        __syncthreads();
        #pragma unroll
        for (int k = 0; k < 16; ++k) {
            ulonglong2 bv = *(const ulonglong2*)&Bs[k][tx * 4];
            const float* ap = &As[k][ty * 4];
            #pragma unroll
            for (int r = 0; r < 4; ++r) {
                ull a2;
                PACK1(a2, ap[r]);
                FFMA2(acc2[r][0], a2, bv.x);
                FFMA2(acc2[r][1], a2, bv.y);
            }
        }
        __syncthreads();
    }
    #pragma unroll
    for (int r = 0; r < 4; ++r) {
        int m = bm * 64 + ty * 4 + r;
        int o = bn * 64 + tx * 4;
        float c0, c1, c2, c3;
        UNPACK2(c0, c1, acc2[r][0]);
        UNPACK2(c2, c3, acc2[r][1]);
        float* dst = &d_xW1[(size_t)m * 768 + o];
        dst[0] = c0 + bih1[o];
        dst[1] = c1 + bih1[o + 1];
        dst[2] = c2 + bih1[o + 2];
        dst[3] = c3 + bih1[o + 3];
    }
}

// ---------------- fused 1D GRU: 32 independent batch rows, f32x2 ----------------
__global__ void __launch_bounds__(384) gru1d_kernel(const float* __restrict__ bhh) {
    __shared__ float h[256];
    __shared__ float gh[768];
    const int tid = threadIdx.x;
    const int b = blockIdx.x;
    const float* __restrict__ xW = d_xW1 + (size_t)b * 64 * 768;
    const int o = tid * 2;
    ull bias2;
    PACKAB(bias2, bhh[o], bhh[o + 1]);

    if (tid < 256) h[tid] = 0.f;
    __syncthreads();

    for (int t = 0; t < TSTEP; ++t) {
        ull acc_a = bias2, acc_b = 0ull;
        #pragma unroll 4
        for (int k = 0; k < 256; k += 2) {
            ull h0, h1;
            PACK1(h0, h[k]);
            PACK1(h1, h[k + 1]);
            ull w0 = *(const ull*)&d_WhT1[(size_t)k * 768 + o];
            ull w1 = *(const ull*)&d_WhT1[(size_t)(k + 1) * 768 + o];
            FFMA2(acc_a, h0, w0);
            FFMA2(acc_b, h1, w1);
        }
        ull acc;
        ADD2(acc, acc_a, acc_b);
        float g0, g1;
        UNPACK2(g0, g1, acc);
        gh[o] = g0; gh[o + 1] = g1;
        __syncthreads();
        if (tid < 256) {
            const float* xwt = xW + t * 768;
            float r = sigm(xwt[tid] + gh[tid]);
            float z = sigm(xwt[256 + tid] + gh[256 + tid]);
            float nn = tanhf(xwt[512 + tid] + r * gh[512 + tid]);
            h[tid] = (1.f - z) * nn + z * h[tid];
        }
        __syncthreads();
    }
    if (tid < 256) d_hlast[b * 256 + tid] = h[tid];
}

// ---------------- final pools over f + fc1 + fc2 ----------------
__global__ void __launch_bounds__(256) final_kernel(const float* __restrict__ fc1b,
                                                    const float* __restrict__ fc2W,
                                                    const float* __restrict__ fc2b,
                                                    float* __restrict__ out) {
    __shared__ float g[2992];
    __shared__ float hh[256];
    __shared__ float red[8];
    const int b = blockIdx.x, tid = threadIdx.x;
    const float* fb = d_f + (size_t)b * 64 * INTER;

    for (int c = tid; c < INTER; c += 256) {
        float mx = -1e30f, mn = 1e30f, sm = 0.f;
        for (int n = 0; n < 64; ++n) {
            float v = fb[n * INTER + c];
            mx = fmaxf(mx, v); mn = fminf(mn, v); sm += v;
        }
        g[c] = mx; g[912 + c] = sm * (1.f / 64.f); g[1824 + c] = mn;
    }
    g[2736 + tid] = d_hlast[b * 256 + tid];
    __syncthreads();

    float acc = fc1b[tid];
    #pragma unroll 4
    for (int j = 0; j < 2992; ++j) acc += g[j] * d_fc1WT[(size_t)j * 256 + tid];
    hh[tid] = fmaxf(acc, 0.f);
    __syncthreads();

    float v = hh[tid] * fc2W[tid];
    #pragma unroll
    for (int off = 16; off > 0; off >>= 1) v += __shfl_down_sync(0xffffffffu, v, off);
    if ((tid & 31) == 0) red[tid >> 5] = v;
    __syncthreads();
    if (tid == 0) {
        float s = 0.f;
        #pragma unroll
        for (int i = 0; i < 8; ++i) s += red[i];
        out[b] = s + fc2b[0];
    }
}

// ---------------- launch ----------------
extern "C" void kernel_launch(void* const* d_in, const int* in_sizes, int n_in,
                              void* d_out, int out_size) {
    const float* x1     = (const float*)d_in[0];
    const float* states = (const float*)d_in[1];
    const void*  perm1  = d_in[2];
    const void*  perm2  = d_in[3];
    const float* Wih2   = (const float*)d_in[4];
    const float* Whh2   = (const float*)d_in[5];
    const float* bih2   = (const float*)d_in[6];
    const float* bhh2   = (const float*)d_in[7];
    const float* Wih1   = (const float*)d_in[8];
    const float* Whh1   = (const float*)d_in[9];
    const float* bih1   = (const float*)d_in[10];
    const float* bhh1   = (const float*)d_in[11];
    const float* fc1W   = (const float*)d_in[12];
    const float* fc1b   = (const float*)d_in[13];
    const float* fc2W   = (const float*)d_in[14];
    const float* fc2b   = (const float*)d_in[15];
    float* out = (float*)d_out;

    detect_kernel<<<1, 32>>>((const long long*)perm1);
    prep_kernel<<<7456, 256>>>(Whh2, Wih2, Whh1, Wih1, fc1W);
    pool_kernel<<<1152, 256>>>(states, x1);
    gru2d_kernel<<<256, 256>>>(states, perm1, perm2, bih2, bhh2);
    gemm_xw1_kernel<<<dim3(12, 32), 256>>>(bih1);
    gru1d_kernel<<<32, 384>>>(bhh1);
    final_kernel<<<32, 256>>>(fc1b, fc2W, fc2b, out);
}

// round 4
// speedup vs baseline: 1.7368x; 1.2602x over previous
#include <cuda_runtime.h>
#include <cuda_bf16.h>
#include <math.h>

typedef unsigned long long ull;

// Shapes
#define Bsz   32
#define Ndim  64
#define Hdim  256
#define INTER 912      // 2H + 6C + C1
#define TSTEP 64
#define SEQPB 14       // sequences per gru2d block
#define NBLK2 293      // ceil(4096/14)

// f32x2 packed helpers (sm_100+ PTX; ptxas won't auto-fuse)
#define FFMA2(acc, a, b)   asm("fma.rn.f32x2 %0, %1, %2, %0;" : "+l"(acc) : "l"(a), "l"(b))
#define ADD2(d, a, b)      asm("add.rn.f32x2 %0, %1, %2;" : "=l"(d) : "l"(a), "l"(b))
#define PACK1(d, s)        asm("mov.b64 %0, {%1, %1};" : "=l"(d) : "f"(s))
#define PACKAB(d, lo, hi)  asm("mov.b64 %0, {%1, %2};" : "=l"(d) : "f"(lo), "f"(hi))
#define UNPACK2(lo, hi, s) asm("mov.b64 {%0, %1}, %2;" : "=f"(lo), "=f"(hi) : "l"(s))

// ---------------- scratch (device globals; no cudaMalloc allowed) ----------------
__device__ float d_f[Bsz * Ndim * INTER];        // fused feature tensor [B,N,912]
__device__ float d_xW1[Bsz * Ndim * 768];        // precomputed f @ Wih1^T + bih1
__device__ float d_W2p[80 * 768 * 4];            // gru2d packed: [k/4][g*256+o][kk]; chunks 0..63=Whh, 64..79=Wih
__device__ float d_WhT1[256 * 768];              // gru1d Whh transposed [k][o]
__device__ float d_WiT1[912 * 768];              // gru1d Wih transposed
__device__ float d_fc1WT[2992 * 256];            // fc1 W transposed [j][o]
__device__ float d_hlast[Bsz * Hdim];
__device__ int   d_perm_is32;

__device__ __forceinline__ float sigm(float x) { return 1.f / (1.f + __expf(-x)); }

// ---------------- perm dtype probe (int64 vs int32) ----------------
__global__ void detect_kernel(const long long* __restrict__ p) {
    if (threadIdx.x == 0 && blockIdx.x == 0) {
        int is32 = 0;
        for (int i = 0; i < 32; ++i) {
            long long v = p[i];
            if (v < 0 || v >= 64) is32 = 1;   // int32 data read as int64 overflows range
        }
        d_perm_is32 = is32;
    }
}

// ---------------- weight transposes / packing ----------------
// segments: W2p(245760) WhT1(196608) WiT1(700416) fc1WT(765952) -> 1908736
__global__ void prep_kernel(const float* __restrict__ Whh2, const float* __restrict__ Wih2,
                            const float* __restrict__ Whh1, const float* __restrict__ Wih1,
                            const float* __restrict__ fc1W) {
    int i = blockIdx.x * blockDim.x + threadIdx.x;
    if (i < 245760) {
        int c = i / 3072;           // chunk stride = 768*4 = 3072 floats (R3 bug: used 4096)
        int rem = i % 3072;
        int o = rem >> 2, kk = rem & 3;   // o = g*256 + out-channel (0..767)
        if (c < 64) d_W2p[i] = Whh2[o * 256 + (4 * c + kk)];
        else        d_W2p[i] = Wih2[o * 64 + (4 * (c - 64) + kk)];
    } else if (i < 442368) {
        int j = i - 245760; int k = j / 768, o = j % 768;
        d_WhT1[j] = Whh1[o * 256 + k];
    } else if (i < 1142784) {
        int j = i - 442368; int k = j / 768, o = j % 768;
        d_WiT1[j] = Wih1[o * 912 + k];
    } else if (i < 1908736) {
        int j = i - 1142784; int o = j % 256, j2 = j / 256;
        d_fc1WT[j] = fc1W[o * 2992 + j2];
    }
}

// ---------------- pools over states + x1 copy into f ----------------
__global__ void pool_kernel(const float* __restrict__ states, const float* __restrict__ x1) {
    int i = blockIdx.x * blockDim.x + threadIdx.x;
    if (i < 131072) {
        int c = i & 63, j = (i >> 6) & 63, b = i >> 12;
        float mx = -1e30f, mn = 1e30f, sm = 0.f;
        for (int n = 0; n < 64; ++n) {
            float v = states[(((b * 64 + n) * 64 + j) << 6) + c];
            mx = fmaxf(mx, v); mn = fminf(mn, v); sm += v;
        }
        float* fp = d_f + (size_t)(b * 64 + j) * INTER;
        fp[16 + c] = mx; fp[80 + c] = sm * (1.f / 64.f); fp[144 + c] = mn;
    } else if (i < 262144) {
        int i2 = i - 131072;
        int c = i2 & 63, n = (i2 >> 6) & 63, b = i2 >> 12;
        float mx = -1e30f, mn = 1e30f, sm = 0.f;
        const float* row = states + (((size_t)(b * 64 + n) * 64) << 6) + c;
        for (int m = 0; m < 64; ++m) {
            float v = row[m << 6];
            mx = fmaxf(mx, v); mn = fminf(mn, v); sm += v;
        }
        float* fp = d_f + (size_t)(b * 64 + n) * INTER;
        fp[208 + c] = mx; fp[272 + c] = sm * (1.f / 64.f); fp[336 + c] = mn;
    } else if (i < 294912) {
        int i3 = i - 262144;
        d_f[(size_t)(i3 >> 4) * INTER + (i3 & 15)] = x1[i3];
    }
}

// ---------------- gather helper for gru2d ----------------
__device__ __forceinline__ float gather_one(const float* __restrict__ states, int seq0, int i, int tt,
        int is32, const int* __restrict__ p1_32, const long long* __restrict__ p1_64,
        const int* __restrict__ p2_32, const long long* __restrict__ p2_64) {
    int si = i >> 6, c = i & 63, s = seq0 + si;
    if (s >= 4096) return 0.f;
    const float* src;
    if (s < 2048) {
        int b = s >> 6, n = s & 63;
        int m = is32 ? p1_32[n * 64 + tt] : (int)p1_64[n * 64 + tt];
        src = states + (((size_t)((b * 64 + n) * 64 + m)) << 6);
    } else {
        int sp = s - 2048;
        int b = sp >> 6, n = sp & 63;
        int sn = is32 ? p2_32[n * 64 + tt] : (int)p2_64[n * 64 + tt];
        src = states + (((size_t)((b * 64 + sn) * 64 + n)) << 6);
    }
    return __ldg(src + c);
}

// ---------------- fused 2D GRU: 4096 seqs, 14 per block, 293 blocks ----------------
__global__ void __launch_bounds__(256, 2) gru2d_kernel(
    const float* __restrict__ states,
    const void* __restrict__ perm1v, const void* __restrict__ perm2v,
    const float* __restrict__ bih, const float* __restrict__ bhh) {
    __shared__ float hT[256][16];     // [k][seq] (14 used)
    __shared__ float xT[2][64][16];   // double-buffered gathered x
    const int tid = threadIdx.x;
    const int seq0 = blockIdx.x * SEQPB;
    const int is32 = d_perm_is32;
    const long long* __restrict__ p1_64 = (const long long*)perm1v;
    const long long* __restrict__ p2_64 = (const long long*)perm2v;
    const int* __restrict__ p1_32 = (const int*)perm1v;
    const int* __restrict__ p2_32 = (const int*)perm2v;
    const float4* __restrict__ Wp4 = (const float4*)d_W2p;

    const float b_r  = bih[tid]       + bhh[tid];
    const float b_z  = bih[256 + tid] + bhh[256 + tid];
    const float b_in = bih[512 + tid];
    const float b_hn = bhh[512 + tid];

    for (int i = tid; i < 256 * 16; i += 256) (&hT[0][0])[i] = 0.f;
    // initial gather (t=0) into xT[0]
    for (int i = tid; i < SEQPB * 64; i += 256) {
        float v = gather_one(states, seq0, i, 0, is32, p1_32, p1_64, p2_32, p2_64);
        xT[0][i & 63][i >> 6] = v;
    }
    __syncthreads();

    int cur = 0;
    for (int t = 0; t < TSTEP; ++t) {
        // prefetch next step's x into registers (hidden under compute)
        float px0 = 0.f, px1 = 0.f, px2 = 0.f, px3 = 0.f;
        if (t < TSTEP - 1) {
            px0 = gather_one(states, seq0, tid,       t + 1, is32, p1_32, p1_64, p2_32, p2_64);
            px1 = gather_one(states, seq0, tid + 256, t + 1, is32, p1_32, p1_64, p2_32, p2_64);
            px2 = gather_one(states, seq0, tid + 512, t + 1, is32, p1_32, p1_64, p2_32, p2_64);
            if (tid < SEQPB * 64 - 768)
                px3 = gather_one(states, seq0, tid + 768, t + 1, is32, p1_32, p1_64, p2_32, p2_64);
        }

        ull accr[7], accz[7], accn[7], acci[7];
        #pragma unroll
        for (int p = 0; p < 7; ++p) { accr[p] = 0ull; accz[p] = 0ull; accn[p] = 0ull; acci[p] = 0ull; }

        // recurrent part: chunks 0..63 (K=256), double-buffered weights
        float4 wr = Wp4[tid], wz = Wp4[256 + tid], wn = Wp4[512 + tid];
        #pragma unroll 2
        for (int c = 0; c < 64; ++c) {
            const int cn = c + 1;   // c=63 prefetches chunk 64 (first input chunk)
            float4 nr = Wp4[cn * 768 + tid];
            float4 nz = Wp4[cn * 768 + 256 + tid];
            float4 nn4 = Wp4[cn * 768 + 512 + tid];
            #pragma unroll
            for (int kk = 0; kk < 4; ++kk) {
                const int k = 4 * c + kk;
                const ulonglong2* hp = (const ulonglong2*)&hT[k][0];
                ulonglong2 A = hp[0], Bv = hp[1], Cv = hp[2];
                ull Dv = *(const ull*)&hT[k][12];
                ull hv[7] = {A.x, A.y, Bv.x, Bv.y, Cv.x, Cv.y, Dv};
                float wrs = (kk == 0) ? wr.x : (kk == 1) ? wr.y : (kk == 2) ? wr.z : wr.w;
                float wzs = (kk == 0) ? wz.x : (kk == 1) ? wz.y : (kk == 2) ? wz.z : wz.w;
                float wns = (kk == 0) ? wn.x : (kk == 1) ? wn.y : (kk == 2) ? wn.z : wn.w;
                ull w2r, w2z, w2n;
                PACK1(w2r, wrs); PACK1(w2z, wzs); PACK1(w2n, wns);
                #pragma unroll
                for (int p = 0; p < 7; ++p) {
                    FFMA2(accr[p], hv[p], w2r);
                    FFMA2(accz[p], hv[p], w2z);
                    FFMA2(accn[p], hv[p], w2n);
                }
            }
            wr = nr; wz = nz; wn = nn4;
        }
        // input part: chunks 64..79 (K=64), source xT[cur], n goes to acci
        {
            const float (*xc)[16] = xT[cur];
            #pragma unroll 2
            for (int c2 = 0; c2 < 16; ++c2) {
                const int cn = (c2 < 15) ? (65 + c2) : 79;
                float4 nr = Wp4[cn * 768 + tid];
                float4 nz = Wp4[cn * 768 + 256 + tid];
                float4 nn4 = Wp4[cn * 768 + 512 + tid];
                #pragma unroll
                for (int kk = 0; kk < 4; ++kk) {
                    const int k = 4 * c2 + kk;
                    const ulonglong2* xp = (const ulonglong2*)&xc[k][0];
                    ulonglong2 A = xp[0], Bv = xp[1], Cv = xp[2];
                    ull Dv = *(const ull*)&xc[k][12];
                    ull xv[7] = {A.x, A.y, Bv.x, Bv.y, Cv.x, Cv.y, Dv};
                    float wrs = (kk == 0) ? wr.x : (kk == 1) ? wr.y : (kk == 2) ? wr.z : wr.w;
                    float wzs = (kk == 0) ? wz.x : (kk == 1) ? wz.y : (kk == 2) ? wz.z : wz.w;
                    float wns = (kk == 0) ? wn.x : (kk == 1) ? wn.y : (kk == 2) ? wn.z : wn.w;
                    ull w2r, w2z, w2n;
                    PACK1(w2r, wrs); PACK1(w2z, wzs); PACK1(w2n, wns);
                    #pragma unroll
                    for (int p = 0; p < 7; ++p) {
                        FFMA2(accr[p], xv[p], w2r);
                        FFMA2(accz[p], xv[p], w2z);
                        FFMA2(acci[p], xv[p], w2n);
                    }
                }
                wr = nr; wz = nz; wn = nn4;
            }
        }

        // publish prefetched x into the other buffer
        if (t < TSTEP - 1) {
            float (*xn)[16] = xT[cur ^ 1];
            const int c = tid & 63, si = tid >> 6;
            xn[c][si] = px0;
            xn[c][si + 4] = px1;
            xn[c][si + 8] = px2;
            if (tid < SEQPB * 64 - 768) xn[c][si + 12] = px3;
        }
        __syncthreads();   // compute done reading hT/xT[cur]; next x published

        // epilogue: activations + h update (channel = tid, 14 seqs)
        float4 h4a = *(const float4*)&hT[tid][0];
        float4 h4b = *(const float4*)&hT[tid][4];
        float4 h4c = *(const float4*)&hT[tid][8];
        float2 h2d = *(const float2*)&hT[tid][12];
        float hold[14] = {h4a.x, h4a.y, h4a.z, h4a.w, h4b.x, h4b.y, h4b.z, h4b.w,
                          h4c.x, h4c.y, h4c.z, h4c.w, h2d.x, h2d.y};
        float hnew[14];
        #pragma unroll
        for (int p = 0; p < 7; ++p) {
            float ar0, ar1, az0, az1, ah0, ah1, ai0, ai1;
            UNPACK2(ar0, ar1, accr[p]);
            UNPACK2(az0, az1, accz[p]);
            UNPACK2(ah0, ah1, accn[p]);
            UNPACK2(ai0, ai1, acci[p]);
            float r0 = sigm(ar0 + b_r);
            float z0 = sigm(az0 + b_z);
            float n0 = tanhf(ai0 + b_in + r0 * (ah0 + b_hn));
            hnew[2 * p]     = (1.f - z0) * n0 + z0 * hold[2 * p];
            float r1 = sigm(ar1 + b_r);
            float z1 = sigm(az1 + b_z);
            float n1 = tanhf(ai1 + b_in + r1 * (ah1 + b_hn));
            hnew[2 * p + 1] = (1.f - z1) * n1 + z1 * hold[2 * p + 1];
        }
        *(float4*)&hT[tid][0]  = make_float4(hnew[0], hnew[1], hnew[2], hnew[3]);
        *(float4*)&hT[tid][4]  = make_float4(hnew[4], hnew[5], hnew[6], hnew[7]);
        *(float4*)&hT[tid][8]  = make_float4(hnew[8], hnew[9], hnew[10], hnew[11]);
        *(float2*)&hT[tid][12] = make_float2(hnew[12], hnew[13]);

        if (t == TSTEP - 1) {
            #pragma unroll
            for (int si = 0; si < SEQPB; ++si) {
                int s = seq0 + si;
                if (s < 4096) {
                    int b, n, off;
                    if (s < 2048) { b = s >> 6; n = s & 63; off = 400; }
                    else { int sp = s - 2048; b = sp >> 6; n = sp & 63; off = 656; }
                    d_f[(size_t)(b * 64 + n) * INTER + off + tid] = hnew[si];
                }
            }
        }
        __syncthreads();   // hT published for next step
        cur ^= 1;
    }
}

// ---------------- xW1 = f @ Wih1^T + bih1  (M=2048, K=912, N=768) ----------------
__global__ void __launch_bounds__(256) gemm_xw1_kernel(const float* __restrict__ bih1) {
    __shared__ float As[16][64];
    __shared__ float Bs[16][64];
    const int tid = threadIdx.x;
    const int bn = blockIdx.x;     // 0..11
    const int bm = blockIdx.y;     // 0..31
    const int tx = tid & 15, ty = tid >> 4;
    ull acc2[4][2];
    #pragma unroll
    for (int r = 0; r < 4; ++r) { acc2[r][0] = 0ull; acc2[r][1] = 0ull; }

    for (int k0 = 0; k0 < 912; k0 += 16) {
        for (int l = tid; l < 1024; l += 256) {
            int i = l >> 4, k = l & 15;
            As[k][i] = d_f[(size_t)(bm * 64 + i) * INTER + k0 + k];
        }
        for (int l = tid; l < 1024; l += 256) {
            int k = l >> 6, j = l & 63;
            Bs[k][j] = d_WiT1[(size_t)(k0 + k) * 768 + bn * 64 + j];
        }
        __syncthreads();
        #pragma unroll
        for (int k = 0; k < 16; ++k) {
            ulonglong2 bv = *(const ulonglong2*)&Bs[k][tx * 4];
            const float* ap = &As[k][ty * 4];
            #pragma unroll
            for (int r = 0; r < 4; ++r) {
                ull a2;
                PACK1(a2, ap[r]);
                FFMA2(acc2[r][0], a2, bv.x);
                FFMA2(acc2[r][1], a2, bv.y);
            }
        }
        __syncthreads();
    }
    #pragma unroll
    for (int r = 0; r < 4; ++r) {
        int m = bm * 64 + ty * 4 + r;
        int o = bn * 64 + tx * 4;
        float c0, c1, c2, c3;
        UNPACK2(c0, c1, acc2[r][0]);
        UNPACK2(c2, c3, acc2[r][1]);
        float* dst = &d_xW1[(size_t)m * 768 + o];
        dst[0] = c0 + bih1[o];
        dst[1] = c1 + bih1[o + 1];
        dst[2] = c2 + bih1[o + 2];
        dst[3] = c3 + bih1[o + 3];
    }
}

// ---------------- fused 1D GRU: 32 batch rows, duplicated-h f32x2 ----------------
__global__ void __launch_bounds__(384) gru1d_kernel(const float* __restrict__ bhh) {
    __shared__ float2 hd[256];   // h duplicated per slot for direct f32x2 loads
    __shared__ float gh[768];
    const int tid = threadIdx.x;
    const int b = blockIdx.x;
    const float* __restrict__ xW = d_xW1 + (size_t)b * 64 * 768;
    const int o = tid * 2;
    ull bias2;
    PACKAB(bias2, bhh[o], bhh[o + 1]);

    if (tid < 256) hd[tid] = make_float2(0.f, 0.f);
    __syncthreads();

    for (int t = 0; t < TSTEP; ++t) {
        ull acc_a = bias2, acc_b = 0ull;
        #pragma unroll 4
        for (int k = 0; k < 256; k += 2) {
            ull h0 = *(const ull*)&hd[k];
            ull h1 = *(const ull*)&hd[k + 1];
            ull w0 = *(const ull*)&d_WhT1[(size_t)k * 768 + o];
            ull w1 = *(const ull*)&d_WhT1[(size_t)(k + 1) * 768 + o];
            FFMA2(acc_a, h0, w0);
            FFMA2(acc_b, h1, w1);
        }
        ull acc;
        ADD2(acc, acc_a, acc_b);
        *(ull*)&gh[o] = acc;
        __syncthreads();
        if (tid < 256) {
            const float* xwt = xW + t * 768;
            float r = sigm(xwt[tid] + gh[tid]);
            float z = sigm(xwt[256 + tid] + gh[256 + tid]);
            float nn = tanhf(xwt[512 + tid] + r * gh[512 + tid]);
            float hn = (1.f - z) * nn + z * hd[tid].x;
            hd[tid] = make_float2(hn, hn);
        }
        __syncthreads();
    }
    if (tid < 256) d_hlast[b * 256 + tid] = hd[tid].x;
}

// ---------------- final pools over f + fc1 + fc2 ----------------
__global__ void __launch_bounds__(256) final_kernel(const float* __restrict__ fc1b,
                                                    const float* __restrict__ fc2W,
                                                    const float* __restrict__ fc2b,
                                                    float* __restrict__ out) {
    __shared__ float g[2992];
    __shared__ float hh[256];
    __shared__ float red[8];
    const int b = blockIdx.x, tid = threadIdx.x;
    const float* fb = d_f + (size_t)b * 64 * INTER;

    for (int c = tid; c < INTER; c += 256) {
        float mx = -1e30f, mn = 1e30f, sm = 0.f;
        for (int n = 0; n < 64; ++n) {
            float v = fb[n * INTER + c];
            mx = fmaxf(mx, v); mn = fminf(mn, v); sm += v;
        }
        g[c] = mx; g[912 + c] = sm * (1.f / 64.f); g[1824 + c] = mn;
    }
    g[2736 + tid] = d_hlast[b * 256 + tid];
    __syncthreads();

    float acc = fc1b[tid];
    #pragma unroll 4
    for (int j = 0; j < 2992; ++j) acc += g[j] * d_fc1WT[(size_t)j * 256 + tid];
    hh[tid] = fmaxf(acc, 0.f);
    __syncthreads();

    float v = hh[tid] * fc2W[tid];
    #pragma unroll
    for (int off = 16; off > 0; off >>= 1) v += __shfl_down_sync(0xffffffffu, v, off);
    if ((tid & 31) == 0) red[tid >> 5] = v;
    __syncthreads();
    if (tid == 0) {
        float s = 0.f;
        #pragma unroll
        for (int i = 0; i < 8; ++i) s += red[i];
        out[b] = s + fc2b[0];
    }
}

// ---------------- launch ----------------
extern "C" void kernel_launch(void* const* d_in, const int* in_sizes, int n_in,
                              void* d_out, int out_size) {
    const float* x1     = (const float*)d_in[0];
    const float* states = (const float*)d_in[1];
    const void*  perm1  = d_in[2];
    const void*  perm2  = d_in[3];
    const float* Wih2   = (const float*)d_in[4];
    const float* Whh2   = (const float*)d_in[5];
    const float* bih2   = (const float*)d_in[6];
    const float* bhh2   = (const float*)d_in[7];
    const float* Wih1   = (const float*)d_in[8];
    const float* Whh1   = (const float*)d_in[9];
    const float* bih1   = (const float*)d_in[10];
    const float* bhh1   = (const float*)d_in[11];
    const float* fc1W   = (const float*)d_in[12];
    const float* fc1b   = (const float*)d_in[13];
    const float* fc2W   = (const float*)d_in[14];
    const float* fc2b   = (const float*)d_in[15];
    float* out = (float*)d_out;

    detect_kernel<<<1, 32>>>((const long long*)perm1);
    prep_kernel<<<7456, 256>>>(Whh2, Wih2, Whh1, Wih1, fc1W);
    pool_kernel<<<1152, 256>>>(states, x1);
    gru2d_kernel<<<NBLK2, 256>>>(states, perm1, perm2, bih2, bhh2);
    gemm_xw1_kernel<<<dim3(12, 32), 256>>>(bih1);
    gru1d_kernel<<<32, 384>>>(bhh1);
    final_kernel<<<32, 256>>>(fc1b, fc2W, fc2b, out);
}

// round 5
// speedup vs baseline: 1.7456x; 1.0051x over previous
#include <cuda_runtime.h>
#include <cuda_bf16.h>
#include <math.h>

typedef unsigned long long ull;

// Shapes
#define Bsz   32
#define Ndim  64
#define Hdim  256
#define INTER 912      // 2H + 6C + C1
#define TSTEP 64
#define SEQPB 14       // sequences per gru2d block
#define NBLK2 293      // ceil(4096/14)

// f32x2 packed helpers (sm_100+ PTX; ptxas won't auto-fuse)
#define FFMA2(acc, a, b)   asm("fma.rn.f32x2 %0, %1, %2, %0;" : "+l"(acc) : "l"(a), "l"(b))
#define ADD2(d, a, b)      asm("add.rn.f32x2 %0, %1, %2;" : "=l"(d) : "l"(a), "l"(b))
#define PACK1(d, s)        asm("mov.b64 %0, {%1, %1};" : "=l"(d) : "f"(s))
#define PACKAB(d, lo, hi)  asm("mov.b64 %0, {%1, %2};" : "=l"(d) : "f"(lo), "f"(hi))
#define UNPACK2(lo, hi, s) asm("mov.b64 {%0, %1}, %2;" : "=f"(lo), "=f"(hi) : "l"(s))

// ---------------- scratch (device globals; no cudaMalloc allowed) ----------------
__device__ float d_f[Bsz * Ndim * INTER];        // fused feature tensor [B,N,912]
__device__ float d_xW1[Bsz * Ndim * 768];        // precomputed f @ Wih1^T + bih1
__device__ float d_W2p[80 * 768 * 4];            // gru2d packed: [k/4][g*256+o][kk]; chunks 0..63=Whh, 64..79=Wih
__device__ float d_WhT1[256 * 768];              // gru1d Whh transposed [k][o]
__device__ float d_WiT1[912 * 768];              // gru1d Wih transposed
__device__ float d_fc1WT[2992 * 256];            // fc1 W transposed [j][o]
__device__ float d_hlast[Bsz * Hdim];
__device__ int   d_perm_is32;

__device__ __forceinline__ float sigm(float x) { return 1.f / (1.f + __expf(-x)); }

// ---------------- perm dtype probe (int64 vs int32) ----------------
__global__ void detect_kernel(const long long* __restrict__ p) {
    if (threadIdx.x == 0 && blockIdx.x == 0) {
        int is32 = 0;
        for (int i = 0; i < 32; ++i) {
            long long v = p[i];
            if (v < 0 || v >= 64) is32 = 1;   // int32 data read as int64 overflows range
        }
        d_perm_is32 = is32;
    }
}

// ---------------- weight transposes / packing ----------------
// segments: W2p(245760) WhT1(196608) WiT1(700416) fc1WT(765952) -> 1908736
__global__ void prep_kernel(const float* __restrict__ Whh2, const float* __restrict__ Wih2,
                            const float* __restrict__ Whh1, const float* __restrict__ Wih1,
                            const float* __restrict__ fc1W) {
    int i = blockIdx.x * blockDim.x + threadIdx.x;
    if (i < 245760) {
        int c = i / 3072;           // chunk stride = 768*4 = 3072 floats (R3 bug: used 4096)
        int rem = i % 3072;
        int o = rem >> 2, kk = rem & 3;   // o = g*256 + out-channel (0..767)
        if (c < 64) d_W2p[i] = Whh2[o * 256 + (4 * c + kk)];
        else        d_W2p[i] = Wih2[o * 64 + (4 * (c - 64) + kk)];
    } else if (i < 442368) {
        int j = i - 245760; int k = j / 768, o = j % 768;
        d_WhT1[j] = Whh1[o * 256 + k];
    } else if (i < 1142784) {
        int j = i - 442368; int k = j / 768, o = j % 768;
        d_WiT1[j] = Wih1[o * 912 + k];
    } else if (i < 1908736) {
        int j = i - 1142784; int o = j % 256, j2 = j / 256;
        d_fc1WT[j] = fc1W[o * 2992 + j2];
    }
}

// ---------------- pools over states + x1 copy into f ----------------
__global__ void pool_kernel(const float* __restrict__ states, const float* __restrict__ x1) {
    int i = blockIdx.x * blockDim.x + threadIdx.x;
    if (i < 131072) {
        int c = i & 63, j = (i >> 6) & 63, b = i >> 12;
        float mx = -1e30f, mn = 1e30f, sm = 0.f;
        for (int n = 0; n < 64; ++n) {
            float v = states[(((b * 64 + n) * 64 + j) << 6) + c];
            mx = fmaxf(mx, v); mn = fminf(mn, v); sm += v;
        }
        float* fp = d_f + (size_t)(b * 64 + j) * INTER;
        fp[16 + c] = mx; fp[80 + c] = sm * (1.f / 64.f); fp[144 + c] = mn;
    } else if (i < 262144) {
        int i2 = i - 131072;
        int c = i2 & 63, n = (i2 >> 6) & 63, b = i2 >> 12;
        float mx = -1e30f, mn = 1e30f, sm = 0.f;
        const float* row = states + (((size_t)(b * 64 + n) * 64) << 6) + c;
        for (int m = 0; m < 64; ++m) {
            float v = row[m << 6];
            mx = fmaxf(mx, v); mn = fminf(mn, v); sm += v;
        }
        float* fp = d_f + (size_t)(b * 64 + n) * INTER;
        fp[208 + c] = mx; fp[272 + c] = sm * (1.f / 64.f); fp[336 + c] = mn;
    } else if (i < 294912) {
        int i3 = i - 262144;
        d_f[(size_t)(i3 >> 4) * INTER + (i3 & 15)] = x1[i3];
    }
}

// ---------------- gather helper for gru2d ----------------
__device__ __forceinline__ float gather_one(const float* __restrict__ states, int seq0, int i, int tt,
        int is32, const int* __restrict__ p1_32, const long long* __restrict__ p1_64,
        const int* __restrict__ p2_32, const long long* __restrict__ p2_64) {
    int si = i >> 6, c = i & 63, s = seq0 + si;
    if (s >= 4096) return 0.f;
    const float* src;
    if (s < 2048) {
        int b = s >> 6, n = s & 63;
        int m = is32 ? p1_32[n * 64 + tt] : (int)p1_64[n * 64 + tt];
        src = states + (((size_t)((b * 64 + n) * 64 + m)) << 6);
    } else {
        int sp = s - 2048;
        int b = sp >> 6, n = sp & 63;
        int sn = is32 ? p2_32[n * 64 + tt] : (int)p2_64[n * 64 + tt];
        src = states + (((size_t)((b * 64 + sn) * 64 + n)) << 6);
    }
    return __ldg(src + c);
}

// ---------------- fused 2D GRU: 4096 seqs, 14 per block, 293 blocks ----------------
__global__ void __launch_bounds__(256, 2) gru2d_kernel(
    const float* __restrict__ states,
    const void* __restrict__ perm1v, const void* __restrict__ perm2v,
    const float* __restrict__ bih, const float* __restrict__ bhh) {
    __shared__ float hT[256][16];     // [k][seq] (14 used)
    __shared__ float xT[2][64][16];   // double-buffered gathered x
    const int tid = threadIdx.x;
    const int seq0 = blockIdx.x * SEQPB;
    const int is32 = d_perm_is32;
    const long long* __restrict__ p1_64 = (const long long*)perm1v;
    const long long* __restrict__ p2_64 = (const long long*)perm2v;
    const int* __restrict__ p1_32 = (const int*)perm1v;
    const int* __restrict__ p2_32 = (const int*)perm2v;
    const float4* __restrict__ Wp4 = (const float4*)d_W2p;

    const float b_r  = bih[tid]       + bhh[tid];
    const float b_z  = bih[256 + tid] + bhh[256 + tid];
    const float b_in = bih[512 + tid];
    const float b_hn = bhh[512 + tid];

    for (int i = tid; i < 256 * 16; i += 256) (&hT[0][0])[i] = 0.f;
    // initial gather (t=0) into xT[0]
    for (int i = tid; i < SEQPB * 64; i += 256) {
        float v = gather_one(states, seq0, i, 0, is32, p1_32, p1_64, p2_32, p2_64);
        xT[0][i & 63][i >> 6] = v;
    }
    __syncthreads();

    int cur = 0;
    for (int t = 0; t < TSTEP; ++t) {
        // prefetch next step's x into registers (hidden under compute)
        float px0 = 0.f, px1 = 0.f, px2 = 0.f, px3 = 0.f;
        if (t < TSTEP - 1) {
            px0 = gather_one(states, seq0, tid,       t + 1, is32, p1_32, p1_64, p2_32, p2_64);
            px1 = gather_one(states, seq0, tid + 256, t + 1, is32, p1_32, p1_64, p2_32, p2_64);
            px2 = gather_one(states, seq0, tid + 512, t + 1, is32, p1_32, p1_64, p2_32, p2_64);
            if (tid < SEQPB * 64 - 768)
                px3 = gather_one(states, seq0, tid + 768, t + 1, is32, p1_32, p1_64, p2_32, p2_64);
        }

        ull accr[7], accz[7], accn[7], acci[7];
        #pragma unroll
        for (int p = 0; p < 7; ++p) { accr[p] = 0ull; accz[p] = 0ull; accn[p] = 0ull; acci[p] = 0ull; }

        // recurrent part: chunks 0..63 (K=256), double-buffered weights
        float4 wr = Wp4[tid], wz = Wp4[256 + tid], wn = Wp4[512 + tid];
        #pragma unroll 2
        for (int c = 0; c < 64; ++c) {
            const int cn = c + 1;   // c=63 prefetches chunk 64 (first input chunk)
            float4 nr = Wp4[cn * 768 + tid];
            float4 nz = Wp4[cn * 768 + 256 + tid];
            float4 nn4 = Wp4[cn * 768 + 512 + tid];
            #pragma unroll
            for (int kk = 0; kk < 4; ++kk) {
                const int k = 4 * c + kk;
                const ulonglong2* hp = (const ulonglong2*)&hT[k][0];
                ulonglong2 A = hp[0], Bv = hp[1], Cv = hp[2];
                ull Dv = *(const ull*)&hT[k][12];
                ull hv[7] = {A.x, A.y, Bv.x, Bv.y, Cv.x, Cv.y, Dv};
                float wrs = (kk == 0) ? wr.x : (kk == 1) ? wr.y : (kk == 2) ? wr.z : wr.w;
                float wzs = (kk == 0) ? wz.x : (kk == 1) ? wz.y : (kk == 2) ? wz.z : wz.w;
                float wns = (kk == 0) ? wn.x : (kk == 1) ? wn.y : (kk == 2) ? wn.z : wn.w;
                ull w2r, w2z, w2n;
                PACK1(w2r, wrs); PACK1(w2z, wzs); PACK1(w2n, wns);
                #pragma unroll
                for (int p = 0; p < 7; ++p) {
                    FFMA2(accr[p], hv[p], w2r);
                    FFMA2(accz[p], hv[p], w2z);
                    FFMA2(accn[p], hv[p], w2n);
                }
            }
            wr = nr; wz = nz; wn = nn4;
        }
        // input part: chunks 64..79 (K=64), source xT[cur], n goes to acci
        {
            const float (*xc)[16] = xT[cur];
            #pragma unroll 2
            for (int c2 = 0; c2 < 16; ++c2) {
                const int cn = (c2 < 15) ? (65 + c2) : 79;
                float4 nr = Wp4[cn * 768 + tid];
                float4 nz = Wp4[cn * 768 + 256 + tid];
                float4 nn4 = Wp4[cn * 768 + 512 + tid];
                #pragma unroll
                for (int kk = 0; kk < 4; ++kk) {
                    const int k = 4 * c2 + kk;
                    const ulonglong2* xp = (const ulonglong2*)&xc[k][0];
                    ulonglong2 A = xp[0], Bv = xp[1], Cv = xp[2];
                    ull Dv = *(const ull*)&xc[k][12];
                    ull xv[7] = {A.x, A.y, Bv.x, Bv.y, Cv.x, Cv.y, Dv};
                    float wrs = (kk == 0) ? wr.x : (kk == 1) ? wr.y : (kk == 2) ? wr.z : wr.w;
                    float wzs = (kk == 0) ? wz.x : (kk == 1) ? wz.y : (kk == 2) ? wz.z : wz.w;
                    float wns = (kk == 0) ? wn.x : (kk == 1) ? wn.y : (kk == 2) ? wn.z : wn.w;
                    ull w2r, w2z, w2n;
                    PACK1(w2r, wrs); PACK1(w2z, wzs); PACK1(w2n, wns);
                    #pragma unroll
                    for (int p = 0; p < 7; ++p) {
                        FFMA2(accr[p], xv[p], w2r);
                        FFMA2(accz[p], xv[p], w2z);
                        FFMA2(acci[p], xv[p], w2n);
                    }
                }
                wr = nr; wz = nz; wn = nn4;
            }
        }

        // publish prefetched x into the other buffer
        if (t < TSTEP - 1) {
            float (*xn)[16] = xT[cur ^ 1];
            const int c = tid & 63, si = tid >> 6;
            xn[c][si] = px0;
            xn[c][si + 4] = px1;
            xn[c][si + 8] = px2;
            if (tid < SEQPB * 64 - 768) xn[c][si + 12] = px3;
        }
        __syncthreads();   // compute done reading hT/xT[cur]; next x published

        // epilogue: activations + h update (channel = tid, 14 seqs)
        float4 h4a = *(const float4*)&hT[tid][0];
        float4 h4b = *(const float4*)&hT[tid][4];
        float4 h4c = *(const float4*)&hT[tid][8];
        float2 h2d = *(const float2*)&hT[tid][12];
        float hold[14] = {h4a.x, h4a.y, h4a.z, h4a.w, h4b.x, h4b.y, h4b.z, h4b.w,
                          h4c.x, h4c.y, h4c.z, h4c.w, h2d.x, h2d.y};
        float hnew[14];
        #pragma unroll
        for (int p = 0; p < 7; ++p) {
            float ar0, ar1, az0, az1, ah0, ah1, ai0, ai1;
            UNPACK2(ar0, ar1, accr[p]);
            UNPACK2(az0, az1, accz[p]);
            UNPACK2(ah0, ah1, accn[p]);
            UNPACK2(ai0, ai1, acci[p]);
            float r0 = sigm(ar0 + b_r);
            float z0 = sigm(az0 + b_z);
            float n0 = tanhf(ai0 + b_in + r0 * (ah0 + b_hn));
            hnew[2 * p]     = (1.f - z0) * n0 + z0 * hold[2 * p];
            float r1 = sigm(ar1 + b_r);
            float z1 = sigm(az1 + b_z);
            float n1 = tanhf(ai1 + b_in + r1 * (ah1 + b_hn));
            hnew[2 * p + 1] = (1.f - z1) * n1 + z1 * hold[2 * p + 1];
        }
        *(float4*)&hT[tid][0]  = make_float4(hnew[0], hnew[1], hnew[2], hnew[3]);
        *(float4*)&hT[tid][4]  = make_float4(hnew[4], hnew[5], hnew[6], hnew[7]);
        *(float4*)&hT[tid][8]  = make_float4(hnew[8], hnew[9], hnew[10], hnew[11]);
        *(float2*)&hT[tid][12] = make_float2(hnew[12], hnew[13]);

        if (t == TSTEP - 1) {
            #pragma unroll
            for (int si = 0; si < SEQPB; ++si) {
                int s = seq0 + si;
                if (s < 4096) {
                    int b, n, off;
                    if (s < 2048) { b = s >> 6; n = s & 63; off = 400; }
                    else { int sp = s - 2048; b = sp >> 6; n = sp & 63; off = 656; }
                    d_f[(size_t)(b * 64 + n) * INTER + off + tid] = hnew[si];
                }
            }
        }
        __syncthreads();   // hT published for next step
        cur ^= 1;
    }
}

// ---------------- xW1 = f @ Wih1^T + bih1  (M=2048, K=912, N=768) ----------------
__global__ void __launch_bounds__(256) gemm_xw1_kernel(const float* __restrict__ bih1) {
    __shared__ float As[16][64];
    __shared__ float Bs[16][64];
    const int tid = threadIdx.x;
    const int bn = blockIdx.x;     // 0..11
    const int bm = blockIdx.y;     // 0..31
    const int tx = tid & 15, ty = tid >> 4;
    ull acc2[4][2];
    #pragma unroll
    for (int r = 0; r < 4; ++r) { acc2[r][0] = 0ull; acc2[r][1] = 0ull; }

    for (int k0 = 0; k0 < 912; k0 += 16) {
        for (int l = tid; l < 1024; l += 256) {
            int i = l >> 4, k = l & 15;
            As[k][i] = d_f[(size_t)(bm * 64 + i) * INTER + k0 + k];
        }
        for (int l = tid; l < 1024; l += 256) {
            int k = l >> 6, j = l & 63;
            Bs[k][j] = d_WiT1[(size_t)(k0 + k) * 768 + bn * 64 + j];
        }
        __syncthreads();
        #pragma unroll
        for (int k = 0; k < 16; ++k) {
            ulonglong2 bv = *(const ulonglong2*)&Bs[k][tx * 4];
            const float* ap = &As[k][ty * 4];
            #pragma unroll
            for (int r = 0; r < 4; ++r) {
                ull a2;
                PACK1(a2, ap[r]);
                FFMA2(acc2[r][0], a2, bv.x);
                FFMA2(acc2[r][1], a2, bv.y);
            }
        }
        __syncthreads();
    }
    #pragma unroll
    for (int r = 0; r < 4; ++r) {
        int m = bm * 64 + ty * 4 + r;
        int o = bn * 64 + tx * 4;
        float c0, c1, c2, c3;
        UNPACK2(c0, c1, acc2[r][0]);
        UNPACK2(c2, c3, acc2[r][1]);
        float* dst = &d_xW1[(size_t)m * 768 + o];
        dst[0] = c0 + bih1[o];
        dst[1] = c1 + bih1[o + 1];
        dst[2] = c2 + bih1[o + 2];
        dst[3] = c3 + bih1[o + 3];
    }
}

// ---------------- fused 1D GRU: 32 batch rows, duplicated-h f32x2 ----------------
__global__ void __launch_bounds__(384) gru1d_kernel(const float* __restrict__ bhh) {
    __shared__ float2 hd[256];   // h duplicated per slot for direct f32x2 loads
    __shared__ float gh[768];
    const int tid = threadIdx.x;
    const int b = blockIdx.x;
    const float* __restrict__ xW = d_xW1 + (size_t)b * 64 * 768;
    const int o = tid * 2;
    ull bias2;
    PACKAB(bias2, bhh[o], bhh[o + 1]);

    if (tid < 256) hd[tid] = make_float2(0.f, 0.f);
    __syncthreads();

    for (int t = 0; t < TSTEP; ++t) {
        ull acc_a = bias2, acc_b = 0ull;
        #pragma unroll 4
        for (int k = 0; k < 256; k += 2) {
            ull h0 = *(const ull*)&hd[k];
            ull h1 = *(const ull*)&hd[k + 1];
            ull w0 = *(const ull*)&d_WhT1[(size_t)k * 768 + o];
            ull w1 = *(const ull*)&d_WhT1[(size_t)(k + 1) * 768 + o];
            FFMA2(acc_a, h0, w0);
            FFMA2(acc_b, h1, w1);
        }
        ull acc;
        ADD2(acc, acc_a, acc_b);
        *(ull*)&gh[o] = acc;
        __syncthreads();
        if (tid < 256) {
            const float* xwt = xW + t * 768;
            float r = sigm(xwt[tid] + gh[tid]);
            float z = sigm(xwt[256 + tid] + gh[256 + tid]);
            float nn = tanhf(xwt[512 + tid] + r * gh[512 + tid]);
            float hn = (1.f - z) * nn + z * hd[tid].x;
            hd[tid] = make_float2(hn, hn);
        }
        __syncthreads();
    }
    if (tid < 256) d_hlast[b * 256 + tid] = hd[tid].x;
}

// ---------------- final pools over f + fc1 + fc2 ----------------
__global__ void __launch_bounds__(256) final_kernel(const float* __restrict__ fc1b,
                                                    const float* __restrict__ fc2W,
                                                    const float* __restrict__ fc2b,
                                                    float* __restrict__ out) {
    __shared__ float g[2992];
    __shared__ float hh[256];
    __shared__ float red[8];
    const int b = blockIdx.x, tid = threadIdx.x;
    const float* fb = d_f + (size_t)b * 64 * INTER;

    for (int c = tid; c < INTER; c += 256) {
        float mx = -1e30f, mn = 1e30f, sm = 0.f;
        for (int n = 0; n < 64; ++n) {
            float v = fb[n * INTER + c];
            mx = fmaxf(mx, v); mn = fminf(mn, v); sm += v;
        }
        g[c] = mx; g[912 + c] = sm * (1.f / 64.f); g[1824 + c] = mn;
    }
    g[2736 + tid] = d_hlast[b * 256 + tid];
    __syncthreads();

    float acc = fc1b[tid];
    #pragma unroll 4
    for (int j = 0; j < 2992; ++j) acc += g[j] * d_fc1WT[(size_t)j * 256 + tid];
    hh[tid] = fmaxf(acc, 0.f);
    __syncthreads();

    float v = hh[tid] * fc2W[tid];
    #pragma unroll
    for (int off = 16; off > 0; off >>= 1) v += __shfl_down_sync(0xffffffffu, v, off);
    if ((tid & 31) == 0) red[tid >> 5] = v;
    __syncthreads();
    if (tid == 0) {
        float s = 0.f;
        #pragma unroll
        for (int i = 0; i < 8; ++i) s += red[i];
        out[b] = s + fc2b[0];
    }
}

// ---------------- launch ----------------
extern "C" void kernel_launch(void* const* d_in, const int* in_sizes, int n_in,
                              void* d_out, int out_size) {
    const float* x1     = (const float*)d_in[0];
    const float* states = (const float*)d_in[1];
    const void*  perm1  = d_in[2];
    const void*  perm2  = d_in[3];
    const float* Wih2   = (const float*)d_in[4];
    const float* Whh2   = (const float*)d_in[5];
    const float* bih2   = (const float*)d_in[6];
    const float* bhh2   = (const float*)d_in[7];
    const float* Wih1   = (const float*)d_in[8];
    const float* Whh1   = (const float*)d_in[9];
    const float* bih1   = (const float*)d_in[10];
    const float* bhh1   = (const float*)d_in[11];
    const float* fc1W   = (const float*)d_in[12];
    const float* fc1b   = (const float*)d_in[13];
    const float* fc2W   = (const float*)d_in[14];
    const float* fc2b   = (const float*)d_in[15];
    float* out = (float*)d_out;

    detect_kernel<<<1, 32>>>((const long long*)perm1);
    prep_kernel<<<7456, 256>>>(Whh2, Wih2, Whh1, Wih1, fc1W);
    pool_kernel<<<1152, 256>>>(states, x1);
    gru2d_kernel<<<NBLK2, 256>>>(states, perm1, perm2, bih2, bhh2);
    gemm_xw1_kernel<<<dim3(12, 32), 256>>>(bih1);
    gru1d_kernel<<<32, 384>>>(bhh1);
    final_kernel<<<32, 256>>>(fc1b, fc2W, fc2b, out);
}